// round 9
// baseline (speedup 1.0000x reference)
#include <cuda_runtime.h>
#include <cuda_bf16.h>

// ---------------------------------------------------------------------------
// VGNN sparse GNN. Round 7: bf16 hi/lo split MMA with interleaved accumulator
// chains (dep distance 1 -> 4), register-cached biases, prefetched gather,
// register scatter. Same math/order as Round 6 (bit-identical epilogues).
// ---------------------------------------------------------------------------

#define N_NODES   10000
#define N_FACTORS 20000
#define N_SEGS    30000
#define N_EDGES   80000
#define SD        64
#define N_STEPS   10
#define NTE       512
#define NTL       512
#define NT_RO     256
#define NBLK      148

__device__ float g_h [N_SEGS * SD];
__device__ float g_c [N_SEGS * SD];
__device__ float g_nm[N_NODES * SD];     // node-targeted messages (atomics)
__device__ float g_f1[N_FACTORS * SD];   // factor messages, edges [0,20000)
__device__ float g_f2[N_FACTORS * SD];   // factor messages, edges [20000,40000)

__device__ __forceinline__ float fsigmoid(float x) {
    return 1.0f / (1.0f + __expf(-x));
}
__device__ __forceinline__ float ftanh(float x) {
    return 2.0f * fsigmoid(2.0f * x) - 1.0f;
}

__device__ __forceinline__ unsigned su32(const void* p) {
    return (unsigned)__cvta_generic_to_shared(p);
}

#define LDSM4(r0, r1, r2, r3, addr)                                          \
    asm volatile("ldmatrix.sync.aligned.m8n8.x4.shared.b16 {%0,%1,%2,%3},[%4];" \
                 : "=r"(r0), "=r"(r1), "=r"(r2), "=r"(r3) : "r"(addr))

__device__ __forceinline__ void mma16(float (&d)[4],
                                      unsigned a0, unsigned a1, unsigned a2, unsigned a3,
                                      unsigned b0, unsigned b1) {
    asm volatile(
        "mma.sync.aligned.m16n8k16.row.col.f32.bf16.bf16.f32 "
        "{%0,%1,%2,%3},{%4,%5,%6,%7},{%8,%9},{%0,%1,%2,%3};"
        : "+f"(d[0]), "+f"(d[1]), "+f"(d[2]), "+f"(d[3])
        : "r"(a0), "r"(a1), "r"(a2), "r"(a3), "r"(b0), "r"(b1));
}

// split (v0,v1) -> packed bf16x2 hi word (lo16=v0) and lo (residual) word
__device__ __forceinline__ void split_pack(float v0, float v1,
                                           unsigned& hw, unsigned& lw) {
    asm("cvt.rn.bf16x2.f32 %0, %1, %2;" : "=r"(hw) : "f"(v1), "f"(v0));
    const float h0 = __uint_as_float(hw << 16);
    const float h1 = __uint_as_float(hw & 0xffff0000u);
    const float r0 = v0 - h0;
    const float r1 = v1 - h1;
    asm("cvt.rn.bf16x2.f32 %0, %1, %2;" : "=r"(lw) : "f"(r1), "f"(r0));
}

// ---------------------------------------------------------------------------
// bf16 arrays: [rows][128] bf16, 256 B/row = 64 words/row.
// word (row, w) at row*64 + (w ^ ((row&7)<<2)).   (LDSM-compatible swizzle)
//
// kloop: per chunk, ALL B fragments loaded first, then 3 passes of MMAs
// round-robin over the accumulators (dep distance NSUB instead of 1).
// Per-accumulator MMA order is unchanged vs previous rounds (hh, hl, lh).
// ---------------------------------------------------------------------------
template <int NSUB>
__device__ __forceinline__ void kloop(int lane,
                                      unsigned Ahi, unsigned Alo,
                                      unsigned Bhi, unsigned Blo,
                                      int m0, int nbase,
                                      float (&d)[NSUB][4]) {
    const int l7 = lane & 7;
    const int sw = l7 << 2;
    const unsigned a_row = (unsigned)(m0 + ((lane >> 3) & 1) * 8 + l7) * 256;
    const int a_kadd = (lane >> 4) * 4;
    const int b_kadd = ((lane >> 3) & 1) * 4;
    constexpr int NP = NSUB / 2;
    unsigned b_row[NP];
#pragma unroll
    for (int p = 0; p < NP; ++p)
        b_row[p] = (unsigned)(nbase + p * 16 + (lane >> 4) * 8 + l7) * 256;

#pragma unroll
    for (int ch = 0; ch < 8; ++ch) {
        const unsigned aoff = a_row + ((unsigned)((ch * 8 + a_kadd) ^ sw) << 2);
        unsigned ah[4], al[4];
        LDSM4(ah[0], ah[1], ah[2], ah[3], Ahi + aoff);
        LDSM4(al[0], al[1], al[2], al[3], Alo + aoff);
        const unsigned bk = (unsigned)((ch * 8 + b_kadd) ^ sw) << 2;
        unsigned bh[NP][4], bl[NP][4];
#pragma unroll
        for (int p = 0; p < NP; ++p) {
            LDSM4(bh[p][0], bh[p][1], bh[p][2], bh[p][3], Bhi + b_row[p] + bk);
            LDSM4(bl[p][0], bl[p][1], bl[p][2], bl[p][3], Blo + b_row[p] + bk);
        }
        // pass 1: ah * bh   (each accumulator touched once per pass)
#pragma unroll
        for (int p = 0; p < NP; ++p) {
            mma16(d[2 * p],     ah[0], ah[1], ah[2], ah[3], bh[p][0], bh[p][1]);
            mma16(d[2 * p + 1], ah[0], ah[1], ah[2], ah[3], bh[p][2], bh[p][3]);
        }
        // pass 2: ah * bl
#pragma unroll
        for (int p = 0; p < NP; ++p) {
            mma16(d[2 * p],     ah[0], ah[1], ah[2], ah[3], bl[p][0], bl[p][1]);
            mma16(d[2 * p + 1], ah[0], ah[1], ah[2], ah[3], bl[p][2], bl[p][3]);
        }
        // pass 3: al * bh
#pragma unroll
        for (int p = 0; p < NP; ++p) {
            mma16(d[2 * p],     al[0], al[1], al[2], al[3], bh[p][0], bh[p][1]);
            mma16(d[2 * p + 1], al[0], al[1], al[2], al[3], bh[p][2], bh[p][3]);
        }
    }
}

// epilogue: +cached bias, relu, split to hi/lo bf16 arrays (pitch 64 words)
template <int NSUB, bool RELU>
__device__ __forceinline__ void store_split(int lane, int m0, int nbase,
                                            float (&d)[NSUB][4],
                                            unsigned* __restrict__ OutHi,
                                            unsigned* __restrict__ OutLo,
                                            const float (&bc)[NSUB][2]) {
    const int g = lane >> 2, t = lane & 3;
    const int sw = g << 2;
    unsigned* oh0 = OutHi + (m0 + g) * 64;
    unsigned* oh1 = OutHi + (m0 + 8 + g) * 64;
    unsigned* ol0 = OutLo + (m0 + g) * 64;
    unsigned* ol1 = OutLo + (m0 + 8 + g) * 64;
#pragma unroll
    for (int j = 0; j < NSUB; ++j) {
        const int c = nbase + j * 8 + 2 * t;
        const float bx = bc[j][0];
        const float by = bc[j][1];
        float v0 = d[j][0] + bx, v1 = d[j][1] + by;
        float v2 = d[j][2] + bx, v3 = d[j][3] + by;
        if (RELU) {
            v0 = fmaxf(v0, 0.f); v1 = fmaxf(v1, 0.f);
            v2 = fmaxf(v2, 0.f); v3 = fmaxf(v3, 0.f);
        }
        unsigned hw0, lw0, hw1, lw1;
        split_pack(v0, v1, hw0, lw0);
        split_pack(v2, v3, hw1, lw1);
        const int wq = (c >> 1) ^ sw;
        oh0[wq] = hw0; ol0[wq] = lw0;
        oh1[wq] = hw1; ol1[wq] = lw1;
    }
}

// gather helpers ------------------------------------------------------------
__device__ __forceinline__ float4 gather_slot(const int* __restrict__ row,
                                              const int* __restrict__ col,
                                              int base, int idx) {
    const int i = idx >> 5, q = idx & 31;
    const int e = base + i;
    const int n = (q < 16) ? __ldg(row + e) : __ldg(col + e);
    const int qq = (q < 16) ? q : q - 16;
    return __ldg(reinterpret_cast<const float4*>(g_h + n * SD) + qq);
}

__device__ __forceinline__ void store_slot(unsigned* __restrict__ xsh,
                                           unsigned* __restrict__ xsl,
                                           int idx, float4 v) {
    const int i = idx >> 5, q = idx & 31;
    unsigned h0, l0, h1, l1;
    split_pack(v.x, v.y, h0, l0);
    split_pack(v.z, v.w, h1, l1);
    const int off = i * 64 + ((q * 2) ^ ((i & 7) << 2));
    *reinterpret_cast<uint2*>(xsh + off) = make_uint2(h0, h1);
    *reinterpret_cast<uint2*>(xsl + off) = make_uint2(l0, l1);
}

// direct message scatter from registers
__device__ __forceinline__ void scatter2(const int* __restrict__ col,
                                         int e, int c, float v0, float v1) {
    if (e < 20000) {
        *reinterpret_cast<float2*>(g_f1 + e * SD + c) = make_float2(v0, v1);
    } else if (e < 40000) {
        *reinterpret_cast<float2*>(g_f2 + (e - 20000) * SD + c) = make_float2(v0, v1);
    } else {
        const int s = __ldg(col + e);
        atomicAdd(g_nm + s * SD + c, v0);
        atomicAdd(g_nm + s * SD + c + 1, v1);
    }
}

// ---------------------------------------------------------------------------
// Edge kernel smem layout (byte offsets):
// ---------------------------------------------------------------------------
#define W1H 0
#define W1L (W1H + 32768)
#define W2H (W1L + 32768)
#define W2L (W2H + 32768)
#define W3H (W2L + 32768)
#define W3L (W3H + 16384)
#define XSH (W3L + 16384)
#define XSL (XSH + 16384)
#define H1H (XSL + 16384)
#define H1L (H1H + 16384)
#define W1A (H1L + 16384)           // fp32 [128][4]
#define E_SMEM_BYTES (W1A + 2048)   // 231424 <= 232448

__global__ void __launch_bounds__(NTE, 1)
k_edge(const int* __restrict__ row, const int* __restrict__ col,
       const float* __restrict__ eattr,
       const float* __restrict__ w1, const float* __restrict__ b1,
       const float* __restrict__ w2, const float* __restrict__ b2,
       const float* __restrict__ w3, const float* __restrict__ b3) {
    extern __shared__ char smc[];
    const int tid = threadIdx.x, wid = tid >> 5, lane = tid & 31;

    unsigned* w1hp = (unsigned*)(smc + W1H);
    unsigned* w1lp = (unsigned*)(smc + W1L);
    unsigned* w2hp = (unsigned*)(smc + W2H);
    unsigned* w2lp = (unsigned*)(smc + W2L);
    unsigned* w3hp = (unsigned*)(smc + W3H);
    unsigned* w3lp = (unsigned*)(smc + W3L);
    unsigned* xshp = (unsigned*)(smc + XSH);
    unsigned* xslp = (unsigned*)(smc + XSL);
    unsigned* h1hp = (unsigned*)(smc + H1H);
    unsigned* h1lp = (unsigned*)(smc + H1L);
    float*    w1a  = (float*)(smc + W1A);

    // ---- weight pre-split ----
    for (int idx = tid; idx < 128 * 64; idx += NTE) {
        const int n = idx >> 6, wq = idx & 63, k = wq * 2;
        const int off = n * 64 + (wq ^ ((n & 7) << 2));
        unsigned hw, lw;
        split_pack(w1[n * 132 + k], w1[n * 132 + k + 1], hw, lw);
        w1hp[off] = hw; w1lp[off] = lw;
        split_pack(w2[n * 128 + k], w2[n * 128 + k + 1], hw, lw);
        w2hp[off] = hw; w2lp[off] = lw;
    }
    for (int idx = tid; idx < 64 * 64; idx += NTE) {
        const int n = idx >> 6, wq = idx & 63, k = wq * 2;
        const int off = n * 64 + (wq ^ ((n & 7) << 2));
        unsigned hw, lw;
        split_pack(w3[n * 128 + k], w3[n * 128 + k + 1], hw, lw);
        w3hp[off] = hw; w3lp[off] = lw;
    }
    for (int idx = tid; idx < 512; idx += NTE)
        w1a[idx] = w1[(idx >> 2) * 132 + 128 + (idx & 3)];
    __syncthreads();

    const int g = lane >> 2, t = lane & 3;
    const int m0  = (wid & 3) * 16;
    const int nb2 = (wid >> 2) * 32;   // layers 1,2 (N=128)
    const int nb3 = (wid >> 2) * 16;   // layer 3   (N=64)

    // register-cached bias slices (loop-invariant)
    float b1c[4][2], b2c[4][2], b3c[2][2];
#pragma unroll
    for (int j = 0; j < 4; ++j) {
        b1c[j][0] = __ldg(b1 + nb2 + j * 8 + 2 * t);
        b1c[j][1] = __ldg(b1 + nb2 + j * 8 + 2 * t + 1);
        b2c[j][0] = __ldg(b2 + nb2 + j * 8 + 2 * t);
        b2c[j][1] = __ldg(b2 + nb2 + j * 8 + 2 * t + 1);
    }
#pragma unroll
    for (int j = 0; j < 2; ++j) {
        b3c[j][0] = __ldg(b3 + nb3 + j * 8 + 2 * t);
        b3c[j][1] = __ldg(b3 + nb3 + j * 8 + 2 * t + 1);
    }

    const unsigned uXSH = su32(smc + XSH), uXSL = su32(smc + XSL);
    const unsigned uH1H = su32(smc + H1H), uH1L = su32(smc + H1L);
    const unsigned uW1H = su32(smc + W1H), uW1L = su32(smc + W1L);
    const unsigned uW2H = su32(smc + W2H), uW2L = su32(smc + W2L);
    const unsigned uW3H = su32(smc + W3H), uW3L = su32(smc + W3L);

    const int n_tiles = N_EDGES / 64;  // 1250

    // prefetch first tile's half-gather into registers
    int tt = blockIdx.x;
    float4 r0, r1;
    if (tt < n_tiles) {
        r0 = gather_slot(row, col, tt * 64, tid);
        r1 = gather_slot(row, col, tt * 64, tid + 512);
    }

    for (; tt < n_tiles; tt += gridDim.x) {
        const int base = tt * 64;

        // ---- populate XS: prefetched half + direct half ----
        {
            const float4 a = gather_slot(row, col, base, tid + 1024);
            const float4 b = gather_slot(row, col, base, tid + 1536);
            store_slot(xshp, xslp, tid, r0);
            store_slot(xshp, xslp, tid + 512, r1);
            store_slot(xshp, xslp, tid + 1024, a);
            store_slot(xshp, xslp, tid + 1536, b);
        }
        __syncthreads();

        // issue next tile's half-gather (lands during the 3 GEMM stages)
        const int ntt = tt + gridDim.x;
        if (ntt < n_tiles) {
            r0 = gather_slot(row, col, ntt * 64, tid);
            r1 = gather_slot(row, col, ntt * 64, tid + 512);
        }

        // ---- layer 1: XS -> H1 (attr folded into init, exact fp32) ----
        {
            float d[4][4];
            const float4 ar0 = __ldg(reinterpret_cast<const float4*>(eattr) + (base + m0 + g));
            const float4 ar1 = __ldg(reinterpret_cast<const float4*>(eattr) + (base + m0 + 8 + g));
#pragma unroll
            for (int j = 0; j < 4; ++j) {
                const int c = nb2 + j * 8 + 2 * t;
                const float4 wA = *reinterpret_cast<const float4*>(w1a + c * 4);
                const float4 wB = *reinterpret_cast<const float4*>(w1a + (c + 1) * 4);
                d[j][0] = ar0.x * wA.x + ar0.y * wA.y + ar0.z * wA.z + ar0.w * wA.w;
                d[j][1] = ar0.x * wB.x + ar0.y * wB.y + ar0.z * wB.z + ar0.w * wB.w;
                d[j][2] = ar1.x * wA.x + ar1.y * wA.y + ar1.z * wA.z + ar1.w * wA.w;
                d[j][3] = ar1.x * wB.x + ar1.y * wB.y + ar1.z * wB.z + ar1.w * wB.w;
            }
            kloop<4>(lane, uXSH, uXSL, uW1H, uW1L, m0, nb2, d);
            store_split<4, true>(lane, m0, nb2, d, h1hp, h1lp, b1c);
        }
        __syncthreads();

        // ---- layer 2: H1 -> XS ----
        {
            float d[4][4];
#pragma unroll
            for (int j = 0; j < 4; ++j) { d[j][0] = d[j][1] = d[j][2] = d[j][3] = 0.f; }
            kloop<4>(lane, uH1H, uH1L, uW2H, uW2L, m0, nb2, d);
            store_split<4, true>(lane, m0, nb2, d, xshp, xslp, b2c);
        }
        __syncthreads();

        // ---- layer 3: XS -> messages, scattered straight from registers ----
        {
            float d[2][4];
#pragma unroll
            for (int j = 0; j < 2; ++j) { d[j][0] = d[j][1] = d[j][2] = d[j][3] = 0.f; }
            kloop<2>(lane, uXSH, uXSL, uW3H, uW3L, m0, nb3, d);
            const int e0 = base + m0 + g;
            const int e1 = base + m0 + 8 + g;
#pragma unroll
            for (int j = 0; j < 2; ++j) {
                const int c = nb3 + j * 8 + 2 * t;
                scatter2(col, e0, c, d[j][0] + b3c[j][0], d[j][1] + b3c[j][1]);
                scatter2(col, e1, c, d[j][2] + b3c[j][0], d[j][3] + b3c[j][1]);
            }
        }
        __syncthreads();   // XS/H1 free for next tile
    }
}

// ---------------------------------------------------------------------------
// LSTM kernel. A = [nm|h] (32x128), B = [Wih;Whh] (256x128). bf16 split.
// ---------------------------------------------------------------------------
#define LWCH 0
#define LWCL (LWCH + 65536)
#define LASH (LWCL + 65536)
#define LASL (LASH + 8192)
#define LGT  (LASL + 8192)           // fp32 [32][256]
#define L_SMEM_BYTES (LGT + 32768)   // 180224

__global__ void __launch_bounds__(NTL, 1)
k_lstm(const float* __restrict__ wih, const float* __restrict__ whh,
       const float* __restrict__ bih, const float* __restrict__ bhh) {
    extern __shared__ char smc[];
    const int tid = threadIdx.x, wid = tid >> 5, lane = tid & 31;

    unsigned* wch = (unsigned*)(smc + LWCH);
    unsigned* wcl = (unsigned*)(smc + LWCL);
    unsigned* ash = (unsigned*)(smc + LASH);
    unsigned* asl = (unsigned*)(smc + LASL);
    float*    gt  = (float*)(smc + LGT);

    for (int idx = tid; idx < 256 * 64; idx += NTL) {
        const int n = idx >> 6, wq = idx & 63, k = wq * 2;
        const float v0 = (k < 64) ? wih[n * 64 + k]     : whh[n * 64 + (k - 64)];
        const float v1 = (k < 64) ? wih[n * 64 + k + 1] : whh[n * 64 + (k - 63)];
        unsigned hw, lw;
        split_pack(v0, v1, hw, lw);
        const int off = n * 64 + (wq ^ ((n & 7) << 2));
        wch[off] = hw; wcl[off] = lw;
    }
    __syncthreads();

    const int g = lane >> 2, t = lane & 3;
    const int m0 = (wid & 1) * 16;
    const int nb = (wid >> 1) * 32;

    float bc[4][2];
#pragma unroll
    for (int j = 0; j < 4; ++j) {
        const int c = nb + j * 8 + 2 * t;
        bc[j][0] = __ldg(bih + c) + __ldg(bhh + c);
        bc[j][1] = __ldg(bih + c + 1) + __ldg(bhh + c + 1);
    }

    const unsigned uASH = su32(smc + LASH), uASL = su32(smc + LASL);
    const unsigned uWCH = su32(smc + LWCH), uWCL = su32(smc + LWCL);

    const int n_tiles = (N_SEGS + 31) / 32;  // 938
    for (int tt = blockIdx.x; tt < n_tiles; tt += gridDim.x) {
        const int base = tt * 32;

        // gather A = split([nm | h])
        for (int idx = tid; idx < 32 * 32; idx += NTL) {
            const int i = idx >> 5;
            const int q = idx & 31;
            const int s = base + i;
            float4 v = make_float4(0.f, 0.f, 0.f, 0.f);
            if (s < N_SEGS) {
                if (q < 16) {
                    if (s < N_NODES) {
                        v = reinterpret_cast<const float4*>(g_nm + s * SD)[q];
                    } else {
                        const int f = s - N_NODES;
                        const float4 a = reinterpret_cast<const float4*>(g_f1 + f * SD)[q];
                        const float4 b = reinterpret_cast<const float4*>(g_f2 + f * SD)[q];
                        v = make_float4(a.x + b.x, a.y + b.y, a.z + b.z, a.w + b.w);
                    }
                } else {
                    v = reinterpret_cast<const float4*>(g_h + s * SD)[q - 16];
                }
            }
            unsigned h0, l0, h1, l1;
            split_pack(v.x, v.y, h0, l0);
            split_pack(v.z, v.w, h1, l1);
            const int off = i * 64 + ((q * 2) ^ ((i & 7) << 2));
            *reinterpret_cast<uint2*>(ash + off) = make_uint2(h0, h1);
            *reinterpret_cast<uint2*>(asl + off) = make_uint2(l0, l1);
        }
        __syncthreads();

        // gates = A * [Wih;Whh]^T + b_ih + b_hh   (fp32 out, pitch 256)
        {
            float d[4][4];
#pragma unroll
            for (int j = 0; j < 4; ++j) { d[j][0] = d[j][1] = d[j][2] = d[j][3] = 0.f; }
            kloop<4>(lane, uASH, uASL, uWCH, uWCL, m0, nb, d);
            const int sw = g << 2;
#pragma unroll
            for (int j = 0; j < 4; ++j) {
                const int c = nb + j * 8 + 2 * t;
                const int cc = c ^ sw;
                *reinterpret_cast<float2*>(gt + (m0 + g) * 256 + cc) =
                    make_float2(d[j][0] + bc[j][0], d[j][1] + bc[j][1]);
                *reinterpret_cast<float2*>(gt + (m0 + 8 + g) * 256 + cc) =
                    make_float2(d[j][2] + bc[j][0], d[j][3] + bc[j][1]);
            }
        }
        __syncthreads();

        // elementwise LSTM update + zero node nm
        for (int idx = tid; idx < 32 * 64; idx += NTL) {
            const int i  = idx >> 6;
            const int dd = idx & 63;
            const int s  = base + i;
            if (s < N_SEGS) {
                const int o = dd ^ ((i & 7) << 2);
                const float gi = gt[i * 256 + o];
                const float gf = gt[i * 256 + 64 + o];
                const float gg = gt[i * 256 + 128 + o];
                const float go = gt[i * 256 + 192 + o];
                const float cold = g_c[s * SD + dd];
                const float cn = fsigmoid(gf) * cold + fsigmoid(gi) * ftanh(gg);
                const float hn = fsigmoid(go) * ftanh(cn);
                g_c[s * SD + dd] = cn;
                g_h[s * SD + dd] = hn;
                if (s < N_NODES) g_nm[s * SD + dd] = 0.0f;
            }
        }
        __syncthreads();
    }
}

// ---------------------------------------------------------------------------
__global__ void k_init() {
    int idx = blockIdx.x * blockDim.x + threadIdx.x;
    if (idx >= N_SEGS * SD) return;
    int s = idx >> 6;
    int d = idx & 63;
    g_h[idx] = (s >= N_NODES && d == 0) ? 1.0f : 0.0f;
    g_c[idx] = 0.0f;
    if (s < N_NODES) g_nm[idx] = 0.0f;
}

// ---------------------------------------------------------------------------
// Readout (fp32 SIMT, runs once)
// ---------------------------------------------------------------------------
__device__ __forceinline__ void load_wT(int tid, const float* __restrict__ W,
                                        float* __restrict__ wT,
                                        int N, int K, int WS) {
    for (int idx = tid; idx < N * K; idx += NT_RO) {
        int o = idx / K;
        int k = idx - o * K;
        wT[k * WS + o] = W[idx];
    }
}

template <int N, int K, bool RELU>
__device__ __forceinline__ void gemm_tile64(int tid,
                                            const float* __restrict__ xs,
                                            const float* __restrict__ wT,
                                            const float* __restrict__ bias_g,
                                            float* __restrict__ out) {
    constexpr int OG  = N / 4;
    constexpr int RG  = NT_RO / OG;
    constexpr int EPT = 64 / RG;
    const int oo = tid % OG;
    const int eo = tid / OG;
    const int o  = oo * 4;
    const int e0 = eo * EPT;

    float acc[EPT][4];
    const float4 b4 = __ldg(reinterpret_cast<const float4*>(bias_g) + oo);
#pragma unroll
    for (int ii = 0; ii < EPT; ++ii) {
        acc[ii][0] = b4.x; acc[ii][1] = b4.y; acc[ii][2] = b4.z; acc[ii][3] = b4.w;
    }
#pragma unroll 4
    for (int k = 0; k < K; k += 4) {
        const float4 w0 = *reinterpret_cast<const float4*>(wT + (k + 0) * N + o);
        const float4 w1 = *reinterpret_cast<const float4*>(wT + (k + 1) * N + o);
        const float4 w2 = *reinterpret_cast<const float4*>(wT + (k + 2) * N + o);
        const float4 w3 = *reinterpret_cast<const float4*>(wT + (k + 3) * N + o);
#pragma unroll
        for (int ii = 0; ii < EPT; ++ii) {
            const float4 x4 = *reinterpret_cast<const float4*>(xs + (e0 + ii) * 128 + k);
            acc[ii][0] += x4.x * w0.x + x4.y * w1.x + x4.z * w2.x + x4.w * w3.x;
            acc[ii][1] += x4.x * w0.y + x4.y * w1.y + x4.z * w2.y + x4.w * w3.y;
            acc[ii][2] += x4.x * w0.z + x4.y * w1.z + x4.z * w2.z + x4.w * w3.z;
            acc[ii][3] += x4.x * w0.w + x4.y * w1.w + x4.z * w2.w + x4.w * w3.w;
        }
    }
#pragma unroll
    for (int ii = 0; ii < EPT; ++ii) {
        float4 r;
        r.x = acc[ii][0]; r.y = acc[ii][1]; r.z = acc[ii][2]; r.w = acc[ii][3];
        if (RELU) {
            r.x = fmaxf(r.x, 0.f); r.y = fmaxf(r.y, 0.f);
            r.z = fmaxf(r.z, 0.f); r.w = fmaxf(r.w, 0.f);
        }
        *reinterpret_cast<float4*>(out + (e0 + ii) * N + o) = r;
    }
}

#define R_W1 0
#define R_W2 (R_W1 + 64 * 128)
#define R_W3 (R_W2 + 128 * 128)
#define R_XS (R_W3 + 256)
#define R_H1 (R_XS + 64 * 128)
#define R_LG (R_H1 + 64 * 128)
#define R_SMEM_BYTES ((R_LG + 128) * 4)

__global__ void __launch_bounds__(NT_RO, 1)
k_readout(const float* __restrict__ w1, const float* __restrict__ b1,
          const float* __restrict__ w2, const float* __restrict__ b2,
          const float* __restrict__ w3, const float* __restrict__ b3,
          float* __restrict__ out) {
    extern __shared__ float smf[];
    const int tid = threadIdx.x;

    load_wT(tid, w1, smf + R_W1, 128, 64, 128);
    load_wT(tid, w2, smf + R_W2, 128, 128, 128);
    for (int i = tid; i < 256; i += NT_RO) smf[R_W3 + i] = w3[i];
    __syncthreads();

    const int n_tiles = (N_NODES + 63) / 64;  // 157
    for (int t = blockIdx.x; t < n_tiles; t += gridDim.x) {
        const int base = t * 64;
        for (int idx = tid; idx < 64 * 16; idx += NT_RO) {
            const int i = idx >> 4;
            const int q = idx & 15;
            const int s = base + i;
            float4 v = make_float4(0.f, 0.f, 0.f, 0.f);
            if (s < N_NODES) v = reinterpret_cast<const float4*>(g_h + s * SD)[q];
            reinterpret_cast<float4*>(smf + R_XS + i * 128)[q] = v;
        }
        __syncthreads();

        gemm_tile64<128, 64, true>(tid, smf + R_XS, smf + R_W1, b1, smf + R_H1);
        __syncthreads();
        gemm_tile64<128, 128, true>(tid, smf + R_H1, smf + R_W2, b2, smf + R_XS);
        __syncthreads();

        if (tid < 128) {
            const int i = tid >> 1;
            const int j = tid & 1;
            float acc = __ldg(b3 + j);
#pragma unroll 4
            for (int k = 0; k < 128; ++k)
                acc += smf[R_XS + i * 128 + k] * smf[R_W3 + j * 128 + k];
            smf[R_LG + i * 2 + j] = acc;
        }
        __syncthreads();

        if (tid < 64) {
            const int s = base + tid;
            if (s < N_NODES) {
                const float l0 = smf[R_LG + tid * 2];
                const float l1 = smf[R_LG + tid * 2 + 1];
                const float m  = fmaxf(l0, l1);
                const float e0 = __expf(l0 - m);
                const float e1 = __expf(l1 - m);
                const float inv = 1.0f / (e0 + e1);
                out[s * 2]     = e0 * inv;
                out[s * 2 + 1] = e1 * inv;
            }
        }
        __syncthreads();
    }
}

// ---------------------------------------------------------------------------
extern "C" void kernel_launch(void* const* d_in, const int* in_sizes, int n_in,
                              void* d_out, int out_size) {
    const int*   row   = (const int*)  d_in[0];
    const int*   col   = (const int*)  d_in[1];
    const float* eattr = (const float*)d_in[2];
    const float* mp_w1 = (const float*)d_in[5];
    const float* mp_b1 = (const float*)d_in[6];
    const float* mp_w2 = (const float*)d_in[7];
    const float* mp_b2 = (const float*)d_in[8];
    const float* mp_w3 = (const float*)d_in[9];
    const float* mp_b3 = (const float*)d_in[10];
    const float* w_ih  = (const float*)d_in[11];
    const float* w_hh  = (const float*)d_in[12];
    const float* b_ih  = (const float*)d_in[13];
    const float* b_hh  = (const float*)d_in[14];
    const float* ro_w1 = (const float*)d_in[15];
    const float* ro_b1 = (const float*)d_in[16];
    const float* ro_w2 = (const float*)d_in[17];
    const float* ro_b2 = (const float*)d_in[18];
    const float* ro_w3 = (const float*)d_in[19];
    const float* ro_b3 = (const float*)d_in[20];
    float* out = (float*)d_out;

    cudaFuncSetAttribute(k_edge,    cudaFuncAttributeMaxDynamicSharedMemorySize, E_SMEM_BYTES);
    cudaFuncSetAttribute(k_lstm,    cudaFuncAttributeMaxDynamicSharedMemorySize, L_SMEM_BYTES);
    cudaFuncSetAttribute(k_readout, cudaFuncAttributeMaxDynamicSharedMemorySize, R_SMEM_BYTES);

    k_init<<<(N_SEGS * SD + 255) / 256, 256>>>();

    for (int step = 0; step < N_STEPS; ++step) {
        k_edge<<<NBLK, NTE, E_SMEM_BYTES>>>(row, col, eattr,
                                            mp_w1, mp_b1, mp_w2, mp_b2, mp_w3, mp_b3);
        k_lstm<<<NBLK, NTL, L_SMEM_BYTES>>>(w_ih, w_hh, b_ih, b_hh);
    }

    k_readout<<<NBLK, NT_RO, R_SMEM_BYTES>>>(ro_w1, ro_b1, ro_w2, ro_b2, ro_w3, ro_b3, out);
}